// round 16
// baseline (speedup 1.0000x reference)
#include <cuda_runtime.h>
#include <cstdint>

#define DIM 512
#define NSTEP 50

typedef unsigned long long u64;

__device__ float g_loss_accum;
__device__ float2 g_ae[NSTEP + 1];   // per-step {invA_t, E_t/A_t}

__device__ __forceinline__ float rsqrt_approx(float x) {
    float y; asm("rsqrt.approx.f32 %0, %1;" : "=f"(y) : "f"(x)); return y;
}
__device__ __forceinline__ float sqrt_approx(float x) {
    float y; asm("sqrt.approx.f32 %0, %1;" : "=f"(y) : "f"(x)); return y;
}
__device__ __forceinline__ u64 pk2(float lo, float hi) {
    u64 r; asm("mov.b64 %0, {%1,%2};" : "=l"(r) : "f"(lo), "f"(hi)); return r;
}
__device__ __forceinline__ void unpk2(float& lo, float& hi, u64 v) {
    asm("mov.b64 {%0,%1}, %2;" : "=f"(lo), "=f"(hi) : "l"(v));
}
__device__ __forceinline__ u64 pk2i(unsigned lo, unsigned hi) {
    u64 r; asm("mov.b64 %0, {%1,%2};" : "=l"(r) : "r"(lo), "r"(hi)); return r;
}
#define FMA2(d, a, b, c) asm("fma.rn.f32x2 %0, %1, %2, %3;" : "=l"(d) : "l"(a), "l"(b), "l"(c))
#define MUL2(d, a, b)    asm("mul.rn.f32x2 %0, %1, %2;"     : "=l"(d) : "l"(a), "l"(b))
#define ADD2(d, a, b)    asm("add.rn.f32x2 %0, %1, %2;"     : "=l"(d) : "l"(a), "l"(b))

// Init: zero loss accumulator; precompute per-step scalars (fp64), one
// thread per step. A is FOLDED into the reciprocal's denominator:
//   ds = sqrt(C2/(1-B2^t)); A_t = LR*C1/((1-B1^t)*ds); E_t = (EPS/S)/ds
//   update: mu -= A*m'/(s+E) = mu - m'/d',  d' = s*(1/A) + E/A
__global__ void wm_init_kernel() {
    const int t = threadIdx.x;
    if (t == 0) g_loss_accum = 0.0f;
    if (t >= 1 && t <= NSTEP) {
        double b1t = pow(0.9, (double)t);
        double b2t = pow(0.999, (double)t);
        double ds = sqrt(0.001 / (1.0 - b2t));
        double A  = 0.01 * 0.1 / ((1.0 - b1t) * ds);
        double E  = (1e-8 * 131072.0) / ds;
        g_ae[t] = make_float2((float)(1.0 / A), (float)(E / A));
    }
}

// TWO rows per warp. R15's lean body reopened a ~50-cyc/step fma bubble
// (serial shfl-reduction convoy). Row B's 208-cyc packed update is
// independent of row A's reduction chain, so the warp always has fma work;
// with ~3 warps/SMSP, pipe demand (2x208 per warp-superstep) >> critical
// path -> saturation at the counted 208 cyc/row. No min-blocks reg cap
// (R9: capping below the live set spills the inner loop).
__global__ __launch_bounds__(64) void wm_kernel(
    const float* __restrict__ mu_in,
    const float* __restrict__ logvar_in,
    const float* __restrict__ carrier,
    float* __restrict__ mu_out,
    float* __restrict__ logvar_out,
    int nrows)
{
    __shared__ float4 s_cN[DIM / 4];   // negated carrier, 2 KB
    __shared__ float blk_loss;

    {
        const float4 cv0 = ((const float4*)carrier)[threadIdx.x];
        const float4 cv1 = ((const float4*)carrier)[threadIdx.x + 64];
        s_cN[threadIdx.x]      = make_float4(-cv0.x, -cv0.y, -cv0.z, -cv0.w);
        s_cN[threadIdx.x + 64] = make_float4(-cv1.x, -cv1.y, -cv1.z, -cv1.w);
        if (threadIdx.x == 0) blk_loss = 0.0f;
    }
    __syncthreads();

    const int wglob = (int)((blockIdx.x * blockDim.x + threadIdx.x) >> 5);
    const int rowA = 2 * wglob;
    const int rowB = rowA + 1;
    const int lane = threadIdx.x & 31;

    const float B1 = 0.9f;
    const float B2 = 0.999f;

    // Packed per-lane state for two rows: 8 f32x2 pairs each
    u64 muA[8], mA[8], vA[8];
    u64 muB[8], mB[8], vB[8];

    if (rowB < nrows) {
        const float4* mrowA = (const float4*)(mu_in + (size_t)rowA * DIM);
        const float4* mrowB = (const float4*)(mu_in + (size_t)rowB * DIM);
        const float4* lrowA = (const float4*)(logvar_in + (size_t)rowA * DIM);
        const float4* lrowB = (const float4*)(logvar_in + (size_t)rowB * DIM);
        float4* loutA = (float4*)(logvar_out + (size_t)rowA * DIM);
        float4* loutB = (float4*)(logvar_out + (size_t)rowB * DIM);

#pragma unroll
        for (int i = 0; i < 4; i++) {
            float4 a = mrowA[lane + 32 * i];
            float4 b = mrowB[lane + 32 * i];
            muA[2 * i]     = pk2(a.x, a.y);
            muA[2 * i + 1] = pk2(a.z, a.w);
            muB[2 * i]     = pk2(b.x, b.y);
            muB[2 * i + 1] = pk2(b.z, b.w);
            loutA[lane + 32 * i] = lrowA[lane + 32 * i];  // log_var passthrough
            loutB[lane + 32 * i] = lrowB[lane + 32 * i];
            mA[2 * i] = 0ull; mA[2 * i + 1] = 0ull;
            vA[2 * i] = 0ull; vA[2 * i + 1] = 0ull;
            mB[2 * i] = 0ull; mB[2 * i + 1] = 0ull;
            vB[2 * i] = 0ull; vB[2 * i + 1] = 0ull;
        }

        const u64 B1_2 = pk2(B1, B1);
        const u64 B2_2 = pk2(B2, B2);
        const u64 ONE2 = pk2(1.0f, 1.0f);

        float lossA = 0.0f, lossB = 0.0f;

        // Initial ||mu||^2 accumulation (steady state tracks only np).
        u64 npaA = 0ull, npaB = 0ull;
#pragma unroll
        for (int p = 0; p < 8; p++) {
            FMA2(npaA, muA[p], muA[p], npaA);
            FMA2(npaB, muB[p], muB[p], npaB);
        }

#pragma unroll 1
        for (int t = 1; t <= NSTEP; ++t) {
            const float2 ae = g_ae[t];
            const float invA = ae.x, EoA = ae.y;

            // Two independent scalar butterflies — chains overlap each other.
            float nlA, nhA, nlB, nhB;
            unpk2(nlA, nhA, npaA);
            unpk2(nlB, nhB, npaB);
            float npA_ = nlA + nhA;
            float npB_ = nlB + nhB;
#pragma unroll
            for (int off = 16; off; off >>= 1) {
                npA_ += __shfl_xor_sync(0xffffffffu, npA_, off);
                npB_ += __shfl_xor_sync(0xffffffffu, npB_, off);
            }

            const float rnormA = rsqrt_approx(npA_);
            const float rnormB = rsqrt_approx(npB_);
            u64 gmaskA = ~0ull, gmaskB = ~0ull;   // hinge ON (Cauchy-Schwarz)

            if (t == NSTEP) {
                // One-time dot pass for the loss (and exact mask), both rows.
                u64 dpaA = 0ull, dpaB = 0ull;
#pragma unroll
                for (int i = 0; i < 4; i++) {
                    float4 c4 = s_cN[lane + 32 * i];
                    u64 ca = pk2(c4.x, c4.y), cb = pk2(c4.z, c4.w);
                    FMA2(dpaA, muA[2 * i],     ca, dpaA);
                    FMA2(dpaA, muA[2 * i + 1], cb, dpaA);
                    FMA2(dpaB, muB[2 * i],     ca, dpaB);
                    FMA2(dpaB, muB[2 * i + 1], cb, dpaB);
                }
                float dlA, dhA, dlB, dhB;
                unpk2(dlA, dhA, dpaA);
                unpk2(dlB, dhB, dpaB);
                float dpnA = dlA + dhA, dpnB = dlB + dhB;   // = -(mu.c)
#pragma unroll
                for (int off = 16; off; off >>= 1) {
                    dpnA += __shfl_xor_sync(0xffffffffu, dpnA, off);
                    dpnB += __shfl_xor_sync(0xffffffffu, dpnB, off);
                }
                // COS_THETA == 1.0f in fp32; margin = norm + dpn (c negated).
                const float marginA = npA_ * rnormA + dpnA;
                const float marginB = npB_ * rnormB + dpnB;
                lossA = fmaxf(marginA, 0.0f);
                lossB = fmaxf(marginB, 0.0f);
                gmaskA = (marginA > 0.0f) ? ~0ull : 0ull;
                gmaskB = (marginB > 0.0f) ? ~0ull : 0ull;
            }

            const u64 rnA2  = pk2(rnormA, rnormA);
            const u64 rnB2  = pk2(rnormB, rnormB);
            const u64 invA2 = pk2(invA, invA);
            const u64 EoA2  = pk2(EoA, EoA);

            npaA = 0ull; npaB = 0ull;

#pragma unroll
            for (int i = 0; i < 4; i++) {
                float4 c4 = s_cN[lane + 32 * i];
                u64 cN[2] = { pk2(c4.x, c4.y), pk2(c4.z, c4.w) };
#pragma unroll
                for (int q = 0; q < 2; q++) {
                    const int p = 2 * i + q;
                    // ---- row A ----
                    {
                        u64 G;
                        FMA2(G, rnA2, muA[p], cN[q]);      // G = mu/||mu|| - c
                        G &= gmaskA;
                        FMA2(mA[p], B1_2, mA[p], G);        // m' = B1*m' + G
                        u64 gg; MUL2(gg, G, G);
                        FMA2(vA[p], B2_2, vA[p], gg);       // v' = B2*v' + G^2
                        float vlo, vhi; unpk2(vlo, vhi, vA[p]);
                        u64 s2 = pk2(sqrt_approx(vlo), sqrt_approx(vhi));
                        u64 dp2; FMA2(dp2, s2, invA2, EoA2);  // (s+E)/A
                        float dlo2, dhi2; unpk2(dlo2, dhi2, dp2);
                        // seed -1/d': bits(-1/d) ~= 0xFEF477D5 - bits(d)
                        u64 y = pk2i(0xFEF477D5u - __float_as_uint(dlo2),
                                     0xFEF477D5u - __float_as_uint(dhi2));
                        // Halley (cubic, err +-4e-5 sign-oscillating; R3:
                        // 1-Newton's biased error compounds over 50 steps)
                        u64 e;  FMA2(e, dp2, y, ONE2);
                        u64 e2; FMA2(e2, e, e, e);
                        u64 w;  FMA2(w, y, e2, y);          // w = -A/(s+E)
                        FMA2(muA[p], w, mA[p], muA[p]);     // mu += w*m
                        FMA2(npaA, muA[p], muA[p], npaA);
                    }
                    // ---- row B (independent chain) ----
                    {
                        u64 G;
                        FMA2(G, rnB2, muB[p], cN[q]);
                        G &= gmaskB;
                        FMA2(mB[p], B1_2, mB[p], G);
                        u64 gg; MUL2(gg, G, G);
                        FMA2(vB[p], B2_2, vB[p], gg);
                        float vlo, vhi; unpk2(vlo, vhi, vB[p]);
                        u64 s2 = pk2(sqrt_approx(vlo), sqrt_approx(vhi));
                        u64 dp2; FMA2(dp2, s2, invA2, EoA2);
                        float dlo2, dhi2; unpk2(dlo2, dhi2, dp2);
                        u64 y = pk2i(0xFEF477D5u - __float_as_uint(dlo2),
                                     0xFEF477D5u - __float_as_uint(dhi2));
                        u64 e;  FMA2(e, dp2, y, ONE2);
                        u64 e2; FMA2(e2, e, e, e);
                        u64 w;  FMA2(w, y, e2, y);
                        FMA2(muB[p], w, mB[p], muB[p]);
                        FMA2(npaB, muB[p], muB[p], npaB);
                    }
                }
            }
        }

        float4* orowA = (float4*)(mu_out + (size_t)rowA * DIM);
        float4* orowB = (float4*)(mu_out + (size_t)rowB * DIM);
#pragma unroll
        for (int i = 0; i < 4; i++) {
            float4 a, b;
            unpk2(a.x, a.y, muA[2 * i]);
            unpk2(a.z, a.w, muA[2 * i + 1]);
            unpk2(b.x, b.y, muB[2 * i]);
            unpk2(b.z, b.w, muB[2 * i + 1]);
            orowA[lane + 32 * i] = a;
            orowB[lane + 32 * i] = b;
        }

        if (lane == 0) atomicAdd(&blk_loss, lossA + lossB);
    }

    __syncthreads();
    if (threadIdx.x == 0) atomicAdd(&g_loss_accum, blk_loss);
}

__global__ void wm_finalize_kernel(float* __restrict__ out_loss) {
    out_loss[0] = g_loss_accum * (1.0f / 131072.0f);
}

extern "C" void kernel_launch(void* const* d_in, const int* in_sizes, int n_in,
                              void* d_out, int out_size) {
    const float* mu      = (const float*)d_in[0];
    const float* log_var = (const float*)d_in[1];
    const float* carrier = (const float*)d_in[2];

    const int n_elem = in_sizes[0];          // 131072 * 512
    const int nrows  = n_elem / DIM;

    float* out        = (float*)d_out;
    float* mu_out     = out;
    float* logvar_out = out + n_elem;
    float* loss_out   = out + 2 * (size_t)n_elem;

    wm_init_kernel<<<1, 64>>>();

    const int threads = 64;                  // 2 warps/block, 2 rows/warp
    const int nwarps  = nrows / 2;
    const int blocks  = (nwarps * 32 + threads - 1) / threads;
    wm_kernel<<<blocks, threads>>>(mu, log_var, carrier, mu_out, logvar_out, nrows);

    wm_finalize_kernel<<<1, 1>>>(loss_out);
}

// round 17
// speedup vs baseline: 1.0543x; 1.0543x over previous
#include <cuda_runtime.h>
#include <cstdint>

#define DIM 512
#define NSTEP 50

typedef unsigned long long u64;

__device__ float2 g_ae[NSTEP + 1];   // per-step {invA_t, E_t/A_t}

__device__ __forceinline__ float rsqrt_approx(float x) {
    float y; asm("rsqrt.approx.f32 %0, %1;" : "=f"(y) : "f"(x)); return y;
}
__device__ __forceinline__ float sqrt_approx(float x) {
    float y; asm("sqrt.approx.f32 %0, %1;" : "=f"(y) : "f"(x)); return y;
}
__device__ __forceinline__ u64 pk2(float lo, float hi) {
    u64 r; asm("mov.b64 %0, {%1,%2};" : "=l"(r) : "f"(lo), "f"(hi)); return r;
}
__device__ __forceinline__ void unpk2(float& lo, float& hi, u64 v) {
    asm("mov.b64 {%0,%1}, %2;" : "=f"(lo), "=f"(hi) : "l"(v));
}
__device__ __forceinline__ u64 pk2i(unsigned lo, unsigned hi) {
    u64 r; asm("mov.b64 %0, {%1,%2};" : "=l"(r) : "r"(lo), "r"(hi)); return r;
}
#define FMA2(d, a, b, c) asm("fma.rn.f32x2 %0, %1, %2, %3;" : "=l"(d) : "l"(a), "l"(b), "l"(c))
#define MUL2(d, a, b)    asm("mul.rn.f32x2 %0, %1, %2;"     : "=l"(d) : "l"(a), "l"(b))
#define ADD2(d, a, b)    asm("add.rn.f32x2 %0, %1, %2;"     : "=l"(d) : "l"(a), "l"(b))

// Init: zero the output loss scalar (graph replays re-zero it every
// iteration); precompute per-step scalars (fp64), one thread per step.
// A is FOLDED into the reciprocal's denominator:
//   ds = sqrt(C2/(1-B2^t)); A_t = LR*C1/((1-B1^t)*ds); E_t = (EPS/S)/ds
//   update: mu -= A*m'/(s+E) = mu - m'/d',  d' = s*(1/A) + E/A
__global__ void wm_init_kernel(float* __restrict__ loss_out) {
    const int t = threadIdx.x;
    if (t == 0) loss_out[0] = 0.0f;
    if (t >= 1 && t <= NSTEP) {
        double b1t = pow(0.9, (double)t);
        double b2t = pow(0.999, (double)t);
        double ds = sqrt(0.001 / (1.0 - b2t));
        double A  = 0.01 * 0.1 / ((1.0 - b1t) * ds);
        double E  = (1e-8 * 131072.0) / ds;
        g_ae[t] = make_float2((float)(1.0 / A), (float)(E / A));
    }
}

// At the FFMA2 banking roofline (R16: two independent ILP doublings were
// neutral => pipe-saturated, not latency-bound). Steady state (t=1..49):
// no dot, no mask, no loss — margin > 0 by Cauchy-Schwarz on this
// trajectory. Step 50 peeled: one dot pass gives exact loss + mask.
__global__ __launch_bounds__(128, 5) void wm_kernel(
    const float* __restrict__ mu_in,
    const float* __restrict__ logvar_in,
    const float* __restrict__ carrier,
    float* __restrict__ mu_out,
    float* __restrict__ logvar_out,
    float* __restrict__ loss_out,
    int nrows)
{
    // Negated carrier in shared memory: identical for every row.
    __shared__ float4 s_cN[DIM / 4];   // 2 KB
    __shared__ float blk_loss;

    {
        const float4 cv = ((const float4*)carrier)[threadIdx.x];
        s_cN[threadIdx.x] = make_float4(-cv.x, -cv.y, -cv.z, -cv.w);
        if (threadIdx.x == 0) blk_loss = 0.0f;
    }
    __syncthreads();

    const int warp = (blockIdx.x * blockDim.x + threadIdx.x) >> 5;
    const int lane = threadIdx.x & 31;

    const float B1 = 0.9f;
    const float B2 = 0.999f;

    // Packed per-lane state: 8 f32x2 pairs each = 16 floats/lane = 512/warp
    u64 mu2[8], m2[8], v2[8];

    if (warp < nrows) {
        const float4* mrow = (const float4*)(mu_in + (size_t)warp * DIM);
        const float4* lrow = (const float4*)(logvar_in + (size_t)warp * DIM);
        float4*       lout = (float4*)(logvar_out + (size_t)warp * DIM);

#pragma unroll
        for (int i = 0; i < 4; i++) {
            float4 a = mrow[lane + 32 * i];
            mu2[2 * i]     = pk2(a.x, a.y);
            mu2[2 * i + 1] = pk2(a.z, a.w);
            lout[lane + 32 * i] = lrow[lane + 32 * i];  // log_var passthrough
            m2[2 * i] = 0ull; m2[2 * i + 1] = 0ull;
            v2[2 * i] = 0ull; v2[2 * i + 1] = 0ull;
        }

        const u64 B1_2 = pk2(B1, B1);
        const u64 B2_2 = pk2(B2, B2);
        const u64 ONE2 = pk2(1.0f, 1.0f);

        // Initial ||mu||^2 partial accumulation.
        u64 npa = 0ull;
#pragma unroll
        for (int p = 0; p < 8; p++) {
            FMA2(npa, mu2[p], mu2[p], npa);
        }

        // ---- steady state: t = 1 .. 49 (no dot / mask / loss) ----
#pragma unroll 1
        for (int t = 1; t < NSTEP; ++t) {
            const float2 ae = g_ae[t];
            const float invA = ae.x, EoA = ae.y;

            float nl, nh;
            unpk2(nl, nh, npa);
            float np = nl + nh;
#pragma unroll
            for (int off = 16; off; off >>= 1)
                np += __shfl_xor_sync(0xffffffffu, np, off);

            const float rnorm = rsqrt_approx(np);        // 1/||mu||

            const u64 rn2   = pk2(rnorm, rnorm);
            const u64 invA2 = pk2(invA, invA);
            const u64 EoA2  = pk2(EoA, EoA);

            npa = 0ull;

#pragma unroll
            for (int i = 0; i < 4; i++) {
                float4 c4 = s_cN[lane + 32 * i];
                u64 cN[2] = { pk2(c4.x, c4.y), pk2(c4.z, c4.w) };
#pragma unroll
                for (int q = 0; q < 2; q++) {
                    const int p = 2 * i + q;
                    u64 G;
                    FMA2(G, rn2, mu2[p], cN[q]);         // G = mu/||mu|| - c
                    FMA2(m2[p], B1_2, m2[p], G);          // m' = B1*m' + G
                    u64 gg; MUL2(gg, G, G);
                    FMA2(v2[p], B2_2, v2[p], gg);         // v' = B2*v' + G^2
                    float vlo, vhi; unpk2(vlo, vhi, v2[p]);
                    u64 s2 = pk2(sqrt_approx(vlo), sqrt_approx(vhi));
                    u64 dp2; FMA2(dp2, s2, invA2, EoA2);  // d' = (s+E)/A
                    float dlo2, dhi2; unpk2(dlo2, dhi2, dp2);
                    // seed -1/d': bits(-1/d) ~= 0xFEF477D5 - bits(d)
                    u64 y = pk2i(0xFEF477D5u - __float_as_uint(dlo2),
                                 0xFEF477D5u - __float_as_uint(dhi2));
                    // Halley (cubic, err +-4e-5 sign-oscillating; R3:
                    // 1-Newton's biased error compounds over 50 steps)
                    u64 e;  FMA2(e, dp2, y, ONE2);        // e = 1 + d'*y
                    u64 e2; FMA2(e2, e, e, e);            // e + e^2
                    u64 w;  FMA2(w, y, e2, y);            // w = -A/(s+E)
                    FMA2(mu2[p], w, m2[p], mu2[p]);       // mu += w*m
                    FMA2(npa, mu2[p], mu2[p], npa);       // next step's norm
                }
            }
        }

        // ---- peeled final step t = 50: exact dot -> loss + mask ----
        {
            const float2 ae = g_ae[NSTEP];
            const float invA = ae.x, EoA = ae.y;

            float nl, nh;
            unpk2(nl, nh, npa);
            float np = nl + nh;
#pragma unroll
            for (int off = 16; off; off >>= 1)
                np += __shfl_xor_sync(0xffffffffu, np, off);
            const float rnorm = rsqrt_approx(np);

            // one-time dot pass
            u64 dpa = 0ull;
#pragma unroll
            for (int i = 0; i < 4; i++) {
                float4 c4 = s_cN[lane + 32 * i];
                FMA2(dpa, mu2[2 * i],     pk2(c4.x, c4.y), dpa);
                FMA2(dpa, mu2[2 * i + 1], pk2(c4.z, c4.w), dpa);
            }
            float dl, dh;
            unpk2(dl, dh, dpa);
            float dpn = dl + dh;           // = -(mu.c)
#pragma unroll
            for (int off = 16; off; off >>= 1)
                dpn += __shfl_xor_sync(0xffffffffu, dpn, off);

            // COS_THETA == 1.0f in fp32; margin = norm + dpn (c negated).
            const float margin = np * rnorm + dpn;
            const float loss_val = fmaxf(margin, 0.0f);
            const u64 gmask = (margin > 0.0f) ? ~0ull : 0ull;

            const u64 rn2   = pk2(rnorm, rnorm);
            const u64 invA2 = pk2(invA, invA);
            const u64 EoA2  = pk2(EoA, EoA);

#pragma unroll
            for (int i = 0; i < 4; i++) {
                float4 c4 = s_cN[lane + 32 * i];
                u64 cN[2] = { pk2(c4.x, c4.y), pk2(c4.z, c4.w) };
#pragma unroll
                for (int q = 0; q < 2; q++) {
                    const int p = 2 * i + q;
                    u64 G;
                    FMA2(G, rn2, mu2[p], cN[q]);
                    G &= gmask;                           // exact hinge mask
                    FMA2(m2[p], B1_2, m2[p], G);
                    u64 gg; MUL2(gg, G, G);
                    FMA2(v2[p], B2_2, v2[p], gg);
                    float vlo, vhi; unpk2(vlo, vhi, v2[p]);
                    u64 s2 = pk2(sqrt_approx(vlo), sqrt_approx(vhi));
                    u64 dp2; FMA2(dp2, s2, invA2, EoA2);
                    float dlo2, dhi2; unpk2(dlo2, dhi2, dp2);
                    u64 y = pk2i(0xFEF477D5u - __float_as_uint(dlo2),
                                 0xFEF477D5u - __float_as_uint(dhi2));
                    u64 e;  FMA2(e, dp2, y, ONE2);
                    u64 e2; FMA2(e2, e, e, e);
                    u64 w;  FMA2(w, y, e2, y);
                    FMA2(mu2[p], w, m2[p], mu2[p]);
                    // no npa accumulation needed after the final step
                }
            }

            if (lane == 0) atomicAdd(&blk_loss, loss_val);
        }

        float4* orow = (float4*)(mu_out + (size_t)warp * DIM);
#pragma unroll
        for (int i = 0; i < 4; i++) {
            float4 a;
            unpk2(a.x, a.y, mu2[2 * i]);
            unpk2(a.z, a.w, mu2[2 * i + 1]);
            orow[lane + 32 * i] = a;
        }
    }

    __syncthreads();
    // Direct scaled accumulation into the output scalar (finalize kernel
    // eliminated; init re-zeroes loss_out every graph replay).
    if (threadIdx.x == 0)
        atomicAdd(loss_out, blk_loss * (1.0f / 131072.0f));
}

extern "C" void kernel_launch(void* const* d_in, const int* in_sizes, int n_in,
                              void* d_out, int out_size) {
    const float* mu      = (const float*)d_in[0];
    const float* log_var = (const float*)d_in[1];
    const float* carrier = (const float*)d_in[2];

    const int n_elem = in_sizes[0];          // 131072 * 512
    const int nrows  = n_elem / DIM;

    float* out        = (float*)d_out;
    float* mu_out     = out;
    float* logvar_out = out + n_elem;
    float* loss_out   = out + 2 * (size_t)n_elem;

    wm_init_kernel<<<1, 64>>>(loss_out);

    const int threads = 128;                 // 4 warps (rows) per block
    const int blocks  = (nrows * 32 + threads - 1) / threads;
    wm_kernel<<<blocks, threads>>>(mu, log_var, carrier, mu_out, logvar_out,
                                   loss_out, nrows);
}